// round 14
// baseline (speedup 1.0000x reference)
#include <cuda_runtime.h>
#include <cuda_bf16.h>
#include <math_constants.h>

#define BB 32
#define DD 256
#define TT 1024
#define KK 8192
#define NN (BB * TT)
#define ZQ_ELEMS (BB * DD * TT)

#define SEGCAP 192
#define NSPLIT 4
#define CAP (SEGCAP * NSPLIT)
#define MARGIN 1.0e-3f
#define TPS 16          // k-tiles per split (64 total / 4)

__device__ float  g_e2[KK];
__device__ float  g_e2p1[KK];
__device__ float  g_t1[NN];
__device__ int    g_idx[NN];
__device__ double g_loss;
__device__ unsigned short g_xbf[NN * DD];
__device__ float          g_xf [NN * DD];
__device__ unsigned short g_ebf[KK * DD];
__device__ unsigned long long g_cand[(size_t)NN * CAP];
__device__ int    g_ccnt4[NN * NSPLIT];
__device__ int    g_runbits[NN];

// ---------------- helpers ----------------
__device__ __forceinline__ unsigned smem_u32(const void* p) {
    unsigned a;
    asm("{ .reg .u64 t; cvta.to.shared.u64 t, %1; cvt.u32.u64 %0, t; }" : "=r"(a) : "l"(p));
    return a;
}
__device__ __forceinline__ void cp16(unsigned dst, const void* src) {
    asm volatile("cp.async.cg.shared.global [%0], [%1], 16;" :: "r"(dst), "l"(src));
}
#define CP_COMMIT() asm volatile("cp.async.commit_group;")
#define CP_WAIT0()  asm volatile("cp.async.wait_group 0;")

__device__ __forceinline__ void ldsm4(unsigned r[4], unsigned addr) {
    asm volatile("ldmatrix.sync.aligned.m8n8.x4.shared.b16 {%0,%1,%2,%3}, [%4];"
                 : "=r"(r[0]), "=r"(r[1]), "=r"(r[2]), "=r"(r[3]) : "r"(addr));
}
__device__ __forceinline__ void mma16816(float c[4], const unsigned a[4], unsigned b0, unsigned b1) {
    asm volatile("mma.sync.aligned.m16n8k16.row.col.f32.bf16.bf16.f32 "
                 "{%0,%1,%2,%3},{%4,%5,%6,%7},{%8,%9},{%0,%1,%2,%3};"
                 : "+f"(c[0]), "+f"(c[1]), "+f"(c[2]), "+f"(c[3])
                 : "r"(a[0]), "r"(a[1]), "r"(a[2]), "r"(a[3]), "r"(b0), "r"(b1));
}
__device__ __forceinline__ unsigned pack_bf2(float a, float b) {
    __nv_bfloat162 h = __floats2bfloat162_rn(a, b);
    return *reinterpret_cast<unsigned*>(&h);
}
// bit-exact sequential chain — MUST NOT be reordered
__device__ __forceinline__ float exact_dist(int n, int k, const float* __restrict__ emb) {
    const float4* xp = (const float4*)(g_xf + (size_t)n * DD);
    const float4* ep = (const float4*)(emb + (size_t)k * DD);
    float dot = 0.f;
#pragma unroll 8
    for (int i = 0; i < 64; i++) {
        float4 xv = xp[i], ev = ep[i];
        dot = __fmaf_rn(xv.x, ev.x, dot);
        dot = __fmaf_rn(xv.y, ev.y, dot);
        dot = __fmaf_rn(xv.z, ev.z, dot);
        dot = __fmaf_rn(xv.w, ev.w, dot);
    }
    return __fsub_rn(__fadd_rn(g_t1[n], g_e2[k]), __fmul_rn(2.0f, dot));
}
// [128 rows][256 bf16] tile, 512B/row, XOR-swizzled 16B pieces; 512 threads
__device__ __forceinline__ void load_tile512(unsigned sbase, const unsigned short* gsrc, int tid) {
#pragma unroll
    for (int t = 0; t < 8; t++) {
        int i = tid + t * 512;
        int row = i >> 5, p = i & 31;
        cp16(sbase + (unsigned)(row * 512 + ((p ^ (row & 7)) << 4)),
             gsrc + (size_t)row * DD + p * 8);
    }
}

// ---------------- prep kernels ----------------
__global__ void prep_eb(const float* __restrict__ emb) {
    int k = blockIdx.x * 8 + (threadIdx.x >> 5);
    int lane = threadIdx.x & 31;
    const float* row = emb + (size_t)k * DD;
    float s = 0.f;
#pragma unroll
    for (int j = 0; j < 8; j++) { float v = row[lane + 32 * j]; s = __fmaf_rn(v, v, s); }
#pragma unroll
    for (int o = 16; o > 0; o >>= 1) s += __shfl_xor_sync(0xffffffffu, s, o);
    if (lane == 0) { g_e2[k] = s; g_e2p1[k] = 1.0f + s; }
    const float4* r4 = (const float4*)row;
    uint2* bo = (uint2*)(g_ebf + (size_t)k * DD);
#pragma unroll
    for (int h = 0; h < 2; h++) {
        float4 v = r4[lane + 32 * h];
        uint2 o;
        o.x = pack_bf2(v.x, v.y);
        o.y = pack_bf2(v.z, v.w);
        bo[lane + 32 * h] = o;
    }
    if (blockIdx.x == 0 && threadIdx.x == 0) g_loss = 0.0;
}

// transpose + convert + t1 (bit-identical sequential chain, from smem)
__global__ void prep_x(const float* __restrict__ ze) {
    __shared__ float sm[32 * 257];
    int n0 = blockIdx.x * 32;
    int b = n0 >> 10, t0 = n0 & 1023;
    int tid = threadIdx.x, w = tid >> 5, l = tid & 31;
    if (tid < 32) g_runbits[n0 + tid] = 0x7F800000;
#pragma unroll
    for (int j = 0; j < 32; j++) {
        int d = w * 32 + j;
        sm[l * 257 + d] = ze[((size_t)b * DD + d) * TT + t0 + l];
    }
    __syncthreads();
    int r = tid >> 3, c = tid & 7;
    float4* xo = (float4*)(g_xf + (size_t)(n0 + r) * DD);
    uint2*  bo = (uint2*)(g_xbf + (size_t)(n0 + r) * DD);
#pragma unroll
    for (int j = 0; j < 8; j++) {
        int ch = c + j * 8;
        float4 v;
        v.x = sm[r * 257 + ch * 4 + 0];
        v.y = sm[r * 257 + ch * 4 + 1];
        v.z = sm[r * 257 + ch * 4 + 2];
        v.w = sm[r * 257 + ch * 4 + 3];
        xo[ch] = v;
        uint2 o; o.x = pack_bf2(v.x, v.y); o.y = pack_bf2(v.z, v.w);
        bo[ch] = o;
    }
    if (tid < 32) {
        float acc = 0.f;
        for (int d = 0; d < DD; d++) {
            float v = sm[tid * 257 + d];
            acc = __fadd_rn(acc, __fmul_rn(v, v));
        }
        g_t1[n0 + tid] = acc;
    }
}

// ---------------- main MMA scan ----------------
#define TILE_BYTES 65536
#define DYN_BYTES (3 * TILE_BYTES)
extern __shared__ unsigned char dyn_smem[];

__global__ __launch_bounds__(512, 1) void vq_mma() {
    __shared__ int runmin_s[128];
    __shared__ int cnt_s[128];
    __shared__ float e2p1_s[2][128];
    const int tid = threadIdx.x, wid = tid >> 5, lane = tid & 31;
    const int wm = wid & 3, wn = wid >> 2;
    const int rb = blockIdx.x & 255, sp = blockIdx.x >> 8;
    const int n0 = rb * 128;

    const unsigned As = smem_u32(dyn_smem);
    const unsigned Es0 = As + TILE_BYTES;
    const unsigned Es1 = As + 2 * TILE_BYTES;

    if (tid < 128) { runmin_s[tid] = 0x7F800000; cnt_s[tid] = 0; }

    load_tile512(As, g_xbf + (size_t)n0 * DD, tid);
    load_tile512(Es0, g_ebf + (size_t)(sp * TPS) * 128 * DD, tid);
    if (tid < 32) cp16(smem_u32(&e2p1_s[0][0]) + tid * 16, g_e2p1 + sp * TPS * 128 + tid * 4);
    CP_COMMIT();
    CP_WAIT0();
    __syncthreads();

    const int g = lane >> 2;

    int rowA[2], rowB[2];
#pragma unroll
    for (int mf = 0; mf < 2; mf++) rowA[mf] = wm * 32 + mf * 16 + (lane & 15);
    {
        int q = lane >> 3;
#pragma unroll
        for (int nf2 = 0; nf2 < 2; nf2++)
            rowB[nf2] = wn * 32 + nf2 * 16 + ((q >> 1) << 3) + (lane & 7);
    }
    const int pA = (lane >> 4);
    const int pB = (lane >> 3) & 1;

    int buf = 0;
    for (int t = 0; t < TPS; t++) {
        const int ktile = sp * TPS + t;
        const unsigned EsC = buf ? Es1 : Es0;
        if (t + 1 < TPS) {
            load_tile512(buf ? Es0 : Es1, g_ebf + (size_t)(ktile + 1) * 128 * DD, tid);
            if (tid < 32)
                cp16(smem_u32(&e2p1_s[buf ^ 1][0]) + tid * 16,
                     g_e2p1 + (ktile + 1) * 128 + tid * 4);
            CP_COMMIT();
        }

        float acc[2][4][4];
#pragma unroll
        for (int mf = 0; mf < 2; mf++)
#pragma unroll
            for (int nf = 0; nf < 4; nf++)
#pragma unroll
                for (int r = 0; r < 4; r++) acc[mf][nf][r] = 0.f;

#pragma unroll
        for (int ks = 0; ks < 16; ks++) {
            unsigned aF[2][4], bF[2][4];
#pragma unroll
            for (int mf = 0; mf < 2; mf++) {
                int row = rowA[mf], p = 2 * ks + pA;
                ldsm4(aF[mf], As + row * 512 + ((p ^ (row & 7)) << 4));
            }
#pragma unroll
            for (int nf2 = 0; nf2 < 2; nf2++) {
                int row = rowB[nf2], p = 2 * ks + pB;
                ldsm4(bF[nf2], EsC + row * 512 + ((p ^ (row & 7)) << 4));
            }
#pragma unroll
            for (int mf = 0; mf < 2; mf++)
#pragma unroll
                for (int nf = 0; nf < 4; nf++)
                    mma16816(acc[mf][nf], aF[mf], bF[nf >> 1][(nf & 1) * 2], bF[nf >> 1][(nf & 1) * 2 + 1]);
        }

        float ea[4], eb[4];
#pragma unroll
        for (int nf = 0; nf < 4; nf++) {
            int cc = wn * 32 + nf * 8 + 2 * (lane & 3);
            ea[nf] = e2p1_s[buf][cc];
            eb[nf] = e2p1_s[buf][cc + 1];
        }

        // phase A: per-thread minima -> shfl over 4 lanes sharing a row -> 1 atomicMin
        {
            float lmin[2][2];
            lmin[0][0] = lmin[0][1] = lmin[1][0] = lmin[1][1] = CUDART_INF_F;
#pragma unroll
            for (int nf = 0; nf < 4; nf++)
#pragma unroll
                for (int mf = 0; mf < 2; mf++)
#pragma unroll
                    for (int rg = 0; rg < 4; rg++) {
                        float s = __fmaf_rn(-2.0f, acc[mf][nf][rg], (rg & 1) ? eb[nf] : ea[nf]);
                        if (s < lmin[mf][rg >> 1]) lmin[mf][rg >> 1] = s;
                    }
#pragma unroll
            for (int mf = 0; mf < 2; mf++)
#pragma unroll
                for (int rh = 0; rh < 2; rh++) {
                    float v = lmin[mf][rh];
                    v = fminf(v, __shfl_xor_sync(0xffffffffu, v, 1));
                    v = fminf(v, __shfl_xor_sync(0xffffffffu, v, 2));
                    if ((lane & 3) == 0)
                        atomicMin(&runmin_s[wm * 32 + mf * 16 + g + rh * 8], __float_as_int(v));
                }
        }
        // Settled-threshold sync only for the first 2 tiles; afterwards the prefix
        // threshold (settled through tile t-1 by the end-of-tile sync) is tight
        // enough, and any slack only ADDS appends (superset stays correct).
        if (t < 2) __syncthreads();

        // phase B: recompute, append vs (>= final) threshold
        {
            float thr[2][2];
#pragma unroll
            for (int mf = 0; mf < 2; mf++)
#pragma unroll
                for (int rh = 0; rh < 2; rh++)
                    thr[mf][rh] = __int_as_float(runmin_s[wm * 32 + mf * 16 + g + rh * 8]) + MARGIN;
            const int kt = ktile * 128;
#pragma unroll
            for (int nf = 0; nf < 4; nf++) {
                const int kb = kt + wn * 32 + nf * 8 + 2 * (lane & 3);
#pragma unroll
                for (int mf = 0; mf < 2; mf++)
#pragma unroll
                    for (int rg = 0; rg < 4; rg++) {
                        float s = __fmaf_rn(-2.0f, acc[mf][nf][rg], (rg & 1) ? eb[nf] : ea[nf]);
                        if (s <= thr[mf][rg >> 1]) {
                            int r = wm * 32 + mf * 16 + g + ((rg >> 1) << 3);
                            int pos = atomicAdd(&cnt_s[r], 1);
                            if (pos < SEGCAP)
                                g_cand[(size_t)(n0 + r) * CAP + sp * SEGCAP + pos] =
                                    ((unsigned long long)(unsigned)__float_as_int(s) << 32) |
                                    (unsigned)(kb + (rg & 1));
                        }
                    }
            }
        }

        CP_WAIT0();
        __syncthreads();
        buf ^= 1;
    }

    if (tid < 128) {
        atomicMin(&g_runbits[n0 + tid], runmin_s[tid]);
        g_ccnt4[(n0 + tid) * NSPLIT + sp] = cnt_s[tid];
    }
}

// ---------------- exact refine: WARP-PER-(ROW,SEGMENT) ----------------
// 2 rows per CTA, 4 warps per row (one per candidate segment, scanned concurrently).
// Lexicographic (dist,k) via packed u64; cross-warp combine in smem.
__global__ void vq_refine(const float* __restrict__ emb, float* __restrict__ out) {
    __shared__ unsigned long long best_s[8];
    const int tid = threadIdx.x;
    const int lane = tid & 31, wid = tid >> 5;
    const int rloc = wid >> 2, sp = wid & 3;       // row-in-CTA, segment
    const int n = blockIdx.x * 2 + rloc;

    int cnts[NSPLIT];
    bool ok = true;
#pragma unroll
    for (int s = 0; s < NSPLIT; s++) {
        cnts[s] = g_ccnt4[n * NSPLIT + s];
        if (cnts[s] > SEGCAP) ok = false;
    }

    unsigned long long best = 0xFFFFFFFFFFFFFFFFull;
    if (ok) {
        const float thr = __int_as_float(g_runbits[n]) + MARGIN;
        const unsigned long long* cl = g_cand + (size_t)n * CAP + sp * SEGCAP;
        for (int i = lane; i < cnts[sp]; i += 32) {
            unsigned long long c = cl[i];
            float s = __int_as_float((int)(c >> 32));
            if (s <= thr) {
                int k = (int)(c & 0xffffffffu);
                float dv = exact_dist(n, k, emb);
                unsigned long long pk =
                    ((unsigned long long)(unsigned)__float_as_int(dv) << 32) | (unsigned)k;
                if (pk < best) best = pk;
            }
        }
    } else {
        for (int k = sp * 2048 + lane; k < (sp + 1) * 2048; k += 32) {
            float dv = exact_dist(n, k, emb);
            unsigned long long pk =
                ((unsigned long long)(unsigned)__float_as_int(dv) << 32) | (unsigned)k;
            if (pk < best) best = pk;
        }
    }
#pragma unroll
    for (int o = 16; o > 0; o >>= 1) {
        unsigned long long v = __shfl_xor_sync(0xffffffffu, best, o);
        if (v < best) best = v;
    }
    if (lane == 0) best_s[wid] = best;
    __syncthreads();
    if (tid < 2) {
        unsigned long long b = best_s[tid * 4];
#pragma unroll
        for (int j = 1; j < 4; j++) {
            unsigned long long v = best_s[tid * 4 + j];
            if (v < b) b = v;
        }
        int bk = (int)(b & 0xffffffffu);
        int nn = blockIdx.x * 2 + tid;
        g_idx[nn] = bk;
        out[ZQ_ELEMS + 1 + nn] = (float)bk;
    }
}

// ---------------- gather + STE + loss ----------------
__global__ void vq_gather(const float* __restrict__ ze, const float* __restrict__ emb,
                          float* __restrict__ out) {
    __shared__ float sm[32 * 257];
    __shared__ double sred[256];
    int n0 = blockIdx.x * 32;
    int b = n0 >> 10, t0 = n0 & 1023;
    int tid = threadIdx.x;
    {
        int r = tid >> 3, c = tid & 7;
        int k = g_idx[n0 + r];
        const float4* er = (const float4*)(emb + (size_t)k * DD);
#pragma unroll
        for (int j = 0; j < 8; j++) {
            int ch = c + j * 8;
            float4 v = er[ch];
            sm[r * 257 + ch * 4 + 0] = v.x;
            sm[r * 257 + ch * 4 + 1] = v.y;
            sm[r * 257 + ch * 4 + 2] = v.z;
            sm[r * 257 + ch * 4 + 3] = v.w;
        }
    }
    __syncthreads();
    int w = tid >> 5, l = tid & 31;
    double lsum = 0.0;
#pragma unroll
    for (int j = 0; j < 32; j++) {
        int d = w * 32 + j;
        size_t off = ((size_t)b * DD + d) * TT + t0 + l;
        float e = sm[l * 257 + d];
        float v = ze[off];
        float diff = __fsub_rn(e, v);
        out[off] = __fadd_rn(v, diff);
        lsum += (double)__fmul_rn(diff, diff);
    }
    sred[tid] = lsum;
    __syncthreads();
    for (int s = 128; s > 0; s >>= 1) {
        if (tid < s) sred[tid] += sred[tid + s];
        __syncthreads();
    }
    if (tid == 0) atomicAdd(&g_loss, sred[0]);
}

__global__ void vq_finalize(float* __restrict__ out) {
    out[ZQ_ELEMS] = (float)(g_loss / (double)ZQ_ELEMS);
}

// ---------------- launch ----------------
extern "C" void kernel_launch(void* const* d_in, const int* in_sizes, int n_in,
                              void* d_out, int out_size) {
    (void)in_sizes; (void)n_in; (void)out_size;
    const float* ze = (const float*)d_in[0];
    const float* emb = (const float*)d_in[1];
    float* out = (float*)d_out;

    cudaFuncSetAttribute(vq_mma, cudaFuncAttributeMaxDynamicSharedMemorySize, DYN_BYTES);

    prep_eb<<<KK / 8, 256>>>(emb);                 // launch 1
    prep_x<<<NN / 32, 256>>>(ze);                  // launch 2
    vq_mma<<<256 * NSPLIT, 512, DYN_BYTES>>>();    // launch 3
    vq_refine<<<NN / 2, 256>>>(emb, out);          // launch 4 <- profiler slot
    vq_gather<<<NN / 32, 256>>>(ze, emb, out);     // launch 5
    vq_finalize<<<1, 1>>>(out);                    // launch 6
}

// round 15
// speedup vs baseline: 1.2124x; 1.2124x over previous
#include <cuda_runtime.h>
#include <cuda_bf16.h>
#include <math_constants.h>

#define BB 32
#define DD 256
#define TT 1024
#define KK 8192
#define NN (BB * TT)
#define ZQ_ELEMS (BB * DD * TT)

#define SEGCAP 192
#define NSPLIT 4
#define CAP (SEGCAP * NSPLIT)
#define MARGIN 1.0e-3f
#define TPS 16          // k-tiles per split (64 total / 4)

__device__ float  g_e2[KK];
__device__ float  g_e2p1[KK];
__device__ float  g_t1[NN];
__device__ int    g_idx[NN];
__device__ double g_loss;
__device__ unsigned short g_xbf[NN * DD];
__device__ float          g_xf [NN * DD];
__device__ unsigned short g_ebf[KK * DD];
__device__ unsigned long long g_cand[(size_t)NN * CAP];
__device__ int    g_ccnt4[NN * NSPLIT];
__device__ int    g_runbits[NN];

// ---------------- helpers ----------------
__device__ __forceinline__ unsigned smem_u32(const void* p) {
    unsigned a;
    asm("{ .reg .u64 t; cvta.to.shared.u64 t, %1; cvt.u32.u64 %0, t; }" : "=r"(a) : "l"(p));
    return a;
}
__device__ __forceinline__ void cp16(unsigned dst, const void* src) {
    asm volatile("cp.async.cg.shared.global [%0], [%1], 16;" :: "r"(dst), "l"(src));
}
#define CP_COMMIT() asm volatile("cp.async.commit_group;")
#define CP_WAIT0()  asm volatile("cp.async.wait_group 0;")

__device__ __forceinline__ void ldsm4(unsigned r[4], unsigned addr) {
    asm volatile("ldmatrix.sync.aligned.m8n8.x4.shared.b16 {%0,%1,%2,%3}, [%4];"
                 : "=r"(r[0]), "=r"(r[1]), "=r"(r[2]), "=r"(r[3]) : "r"(addr));
}
__device__ __forceinline__ void mma16816(float c[4], const unsigned a[4], unsigned b0, unsigned b1) {
    asm volatile("mma.sync.aligned.m16n8k16.row.col.f32.bf16.bf16.f32 "
                 "{%0,%1,%2,%3},{%4,%5,%6,%7},{%8,%9},{%0,%1,%2,%3};"
                 : "+f"(c[0]), "+f"(c[1]), "+f"(c[2]), "+f"(c[3])
                 : "r"(a[0]), "r"(a[1]), "r"(a[2]), "r"(a[3]), "r"(b0), "r"(b1));
}
__device__ __forceinline__ unsigned pack_bf2(float a, float b) {
    __nv_bfloat162 h = __floats2bfloat162_rn(a, b);
    return *reinterpret_cast<unsigned*>(&h);
}
// bit-exact sequential chain — MUST NOT be reordered
__device__ __forceinline__ float exact_dist(int n, int k, const float* __restrict__ emb) {
    const float4* xp = (const float4*)(g_xf + (size_t)n * DD);
    const float4* ep = (const float4*)(emb + (size_t)k * DD);
    float dot = 0.f;
#pragma unroll 8
    for (int i = 0; i < 64; i++) {
        float4 xv = xp[i], ev = ep[i];
        dot = __fmaf_rn(xv.x, ev.x, dot);
        dot = __fmaf_rn(xv.y, ev.y, dot);
        dot = __fmaf_rn(xv.z, ev.z, dot);
        dot = __fmaf_rn(xv.w, ev.w, dot);
    }
    return __fsub_rn(__fadd_rn(g_t1[n], g_e2[k]), __fmul_rn(2.0f, dot));
}
// [128 rows][256 bf16] tile, 512B/row, XOR-swizzled 16B pieces; 512 threads
__device__ __forceinline__ void load_tile512(unsigned sbase, const unsigned short* gsrc, int tid) {
#pragma unroll
    for (int t = 0; t < 8; t++) {
        int i = tid + t * 512;
        int row = i >> 5, p = i & 31;
        cp16(sbase + (unsigned)(row * 512 + ((p ^ (row & 7)) << 4)),
             gsrc + (size_t)row * DD + p * 8);
    }
}

// ---------------- prep kernels ----------------
__global__ void prep_eb(const float* __restrict__ emb) {
    int k = blockIdx.x * 8 + (threadIdx.x >> 5);
    int lane = threadIdx.x & 31;
    const float* row = emb + (size_t)k * DD;
    float s = 0.f;
#pragma unroll
    for (int j = 0; j < 8; j++) { float v = row[lane + 32 * j]; s = __fmaf_rn(v, v, s); }
#pragma unroll
    for (int o = 16; o > 0; o >>= 1) s += __shfl_xor_sync(0xffffffffu, s, o);
    if (lane == 0) { g_e2[k] = s; g_e2p1[k] = 1.0f + s; }
    const float4* r4 = (const float4*)row;
    uint2* bo = (uint2*)(g_ebf + (size_t)k * DD);
#pragma unroll
    for (int h = 0; h < 2; h++) {
        float4 v = r4[lane + 32 * h];
        uint2 o;
        o.x = pack_bf2(v.x, v.y);
        o.y = pack_bf2(v.z, v.w);
        bo[lane + 32 * h] = o;
    }
}

// transpose + convert + t1 (bit-identical sequential chain, from smem)
__global__ void prep_x(const float* __restrict__ ze) {
    __shared__ float sm[32 * 257];
    int n0 = blockIdx.x * 32;
    int b = n0 >> 10, t0 = n0 & 1023;
    int tid = threadIdx.x, w = tid >> 5, l = tid & 31;
    if (tid < 32) g_runbits[n0 + tid] = 0x7F800000;
#pragma unroll
    for (int j = 0; j < 32; j++) {
        int d = w * 32 + j;
        sm[l * 257 + d] = ze[((size_t)b * DD + d) * TT + t0 + l];
    }
    __syncthreads();
    int r = tid >> 3, c = tid & 7;
    float4* xo = (float4*)(g_xf + (size_t)(n0 + r) * DD);
    uint2*  bo = (uint2*)(g_xbf + (size_t)(n0 + r) * DD);
#pragma unroll
    for (int j = 0; j < 8; j++) {
        int ch = c + j * 8;
        float4 v;
        v.x = sm[r * 257 + ch * 4 + 0];
        v.y = sm[r * 257 + ch * 4 + 1];
        v.z = sm[r * 257 + ch * 4 + 2];
        v.w = sm[r * 257 + ch * 4 + 3];
        xo[ch] = v;
        uint2 o; o.x = pack_bf2(v.x, v.y); o.y = pack_bf2(v.z, v.w);
        bo[ch] = o;
    }
    if (tid < 32) {
        float acc = 0.f;
        for (int d = 0; d < DD; d++) {
            float v = sm[tid * 257 + d];
            acc = __fadd_rn(acc, __fmul_rn(v, v));
        }
        g_t1[n0 + tid] = acc;
    }
}

// dummy slot-filler: zero the loss accumulator (launch #3 so vq_mma is #4)
__global__ void zero_loss() { g_loss = 0.0; }

// ---------------- main MMA scan (unchanged from round 14) ----------------
#define TILE_BYTES 65536
#define DYN_BYTES (3 * TILE_BYTES)
extern __shared__ unsigned char dyn_smem[];

__global__ __launch_bounds__(512, 1) void vq_mma() {
    __shared__ int runmin_s[128];
    __shared__ int cnt_s[128];
    __shared__ float e2p1_s[2][128];
    const int tid = threadIdx.x, wid = tid >> 5, lane = tid & 31;
    const int wm = wid & 3, wn = wid >> 2;
    const int rb = blockIdx.x & 255, sp = blockIdx.x >> 8;
    const int n0 = rb * 128;

    const unsigned As = smem_u32(dyn_smem);
    const unsigned Es0 = As + TILE_BYTES;
    const unsigned Es1 = As + 2 * TILE_BYTES;

    if (tid < 128) { runmin_s[tid] = 0x7F800000; cnt_s[tid] = 0; }

    load_tile512(As, g_xbf + (size_t)n0 * DD, tid);
    load_tile512(Es0, g_ebf + (size_t)(sp * TPS) * 128 * DD, tid);
    if (tid < 32) cp16(smem_u32(&e2p1_s[0][0]) + tid * 16, g_e2p1 + sp * TPS * 128 + tid * 4);
    CP_COMMIT();
    CP_WAIT0();
    __syncthreads();

    const int g = lane >> 2;

    int rowA[2], rowB[2];
#pragma unroll
    for (int mf = 0; mf < 2; mf++) rowA[mf] = wm * 32 + mf * 16 + (lane & 15);
    {
        int q = lane >> 3;
#pragma unroll
        for (int nf2 = 0; nf2 < 2; nf2++)
            rowB[nf2] = wn * 32 + nf2 * 16 + ((q >> 1) << 3) + (lane & 7);
    }
    const int pA = (lane >> 4);
    const int pB = (lane >> 3) & 1;

    int buf = 0;
    for (int t = 0; t < TPS; t++) {
        const int ktile = sp * TPS + t;
        const unsigned EsC = buf ? Es1 : Es0;
        if (t + 1 < TPS) {
            load_tile512(buf ? Es0 : Es1, g_ebf + (size_t)(ktile + 1) * 128 * DD, tid);
            if (tid < 32)
                cp16(smem_u32(&e2p1_s[buf ^ 1][0]) + tid * 16,
                     g_e2p1 + (ktile + 1) * 128 + tid * 4);
            CP_COMMIT();
        }

        float acc[2][4][4];
#pragma unroll
        for (int mf = 0; mf < 2; mf++)
#pragma unroll
            for (int nf = 0; nf < 4; nf++)
#pragma unroll
                for (int r = 0; r < 4; r++) acc[mf][nf][r] = 0.f;

#pragma unroll
        for (int ks = 0; ks < 16; ks++) {
            unsigned aF[2][4], bF[2][4];
#pragma unroll
            for (int mf = 0; mf < 2; mf++) {
                int row = rowA[mf], p = 2 * ks + pA;
                ldsm4(aF[mf], As + row * 512 + ((p ^ (row & 7)) << 4));
            }
#pragma unroll
            for (int nf2 = 0; nf2 < 2; nf2++) {
                int row = rowB[nf2], p = 2 * ks + pB;
                ldsm4(bF[nf2], EsC + row * 512 + ((p ^ (row & 7)) << 4));
            }
#pragma unroll
            for (int mf = 0; mf < 2; mf++)
#pragma unroll
                for (int nf = 0; nf < 4; nf++)
                    mma16816(acc[mf][nf], aF[mf], bF[nf >> 1][(nf & 1) * 2], bF[nf >> 1][(nf & 1) * 2 + 1]);
        }

        float ea[4], eb[4];
#pragma unroll
        for (int nf = 0; nf < 4; nf++) {
            int cc = wn * 32 + nf * 8 + 2 * (lane & 3);
            ea[nf] = e2p1_s[buf][cc];
            eb[nf] = e2p1_s[buf][cc + 1];
        }

        // phase A: per-thread minima -> shfl over 4 lanes sharing a row -> 1 atomicMin
        {
            float lmin[2][2];
            lmin[0][0] = lmin[0][1] = lmin[1][0] = lmin[1][1] = CUDART_INF_F;
#pragma unroll
            for (int nf = 0; nf < 4; nf++)
#pragma unroll
                for (int mf = 0; mf < 2; mf++)
#pragma unroll
                    for (int rg = 0; rg < 4; rg++) {
                        float s = __fmaf_rn(-2.0f, acc[mf][nf][rg], (rg & 1) ? eb[nf] : ea[nf]);
                        if (s < lmin[mf][rg >> 1]) lmin[mf][rg >> 1] = s;
                    }
#pragma unroll
            for (int mf = 0; mf < 2; mf++)
#pragma unroll
                for (int rh = 0; rh < 2; rh++) {
                    float v = lmin[mf][rh];
                    v = fminf(v, __shfl_xor_sync(0xffffffffu, v, 1));
                    v = fminf(v, __shfl_xor_sync(0xffffffffu, v, 2));
                    if ((lane & 3) == 0)
                        atomicMin(&runmin_s[wm * 32 + mf * 16 + g + rh * 8], __float_as_int(v));
                }
        }
        if (t < 2) __syncthreads();   // settled threshold for early tiles only

        // phase B: recompute, append vs (>= final) threshold
        {
            float thr[2][2];
#pragma unroll
            for (int mf = 0; mf < 2; mf++)
#pragma unroll
                for (int rh = 0; rh < 2; rh++)
                    thr[mf][rh] = __int_as_float(runmin_s[wm * 32 + mf * 16 + g + rh * 8]) + MARGIN;
            const int kt = ktile * 128;
#pragma unroll
            for (int nf = 0; nf < 4; nf++) {
                const int kb = kt + wn * 32 + nf * 8 + 2 * (lane & 3);
#pragma unroll
                for (int mf = 0; mf < 2; mf++)
#pragma unroll
                    for (int rg = 0; rg < 4; rg++) {
                        float s = __fmaf_rn(-2.0f, acc[mf][nf][rg], (rg & 1) ? eb[nf] : ea[nf]);
                        if (s <= thr[mf][rg >> 1]) {
                            int r = wm * 32 + mf * 16 + g + ((rg >> 1) << 3);
                            int pos = atomicAdd(&cnt_s[r], 1);
                            if (pos < SEGCAP)
                                g_cand[(size_t)(n0 + r) * CAP + sp * SEGCAP + pos] =
                                    ((unsigned long long)(unsigned)__float_as_int(s) << 32) |
                                    (unsigned)(kb + (rg & 1));
                        }
                    }
            }
        }

        CP_WAIT0();
        __syncthreads();
        buf ^= 1;
    }

    if (tid < 128) {
        atomicMin(&g_runbits[n0 + tid], runmin_s[tid]);
        g_ccnt4[(n0 + tid) * NSPLIT + sp] = cnt_s[tid];
    }
}

// ---------------- exact refine: WARP-PER-ROW + BALLOT COMPACTION ----------------
// Pass 1 compacts surviving k's into a per-warp smem list (no chains);
// pass 2 runs ONE lockstep exact-dist chain round over the ~15 survivors.
__global__ void vq_refine(const float* __restrict__ emb, float* __restrict__ out) {
    __shared__ int klist[8][CAP];     // 8 warps x 768 ints = 24 KB; provable max
    const int lane = threadIdx.x & 31, wid = threadIdx.x >> 5;
    const int n = blockIdx.x * 8 + wid;

    int cnts[NSPLIT];
    bool ok = true;
#pragma unroll
    for (int s = 0; s < NSPLIT; s++) {
        cnts[s] = g_ccnt4[n * NSPLIT + s];
        if (cnts[s] > SEGCAP) ok = false;
    }

    unsigned long long best = 0xFFFFFFFFFFFFFFFFull;
    if (ok) {
        const float thr = __int_as_float(g_runbits[n]) + MARGIN;
        const unsigned long long* cl = g_cand + (size_t)n * CAP;
        int m = 0;
        // pass 1: uniform-trip chunked scan, ballot compaction
#pragma unroll
        for (int sp = 0; sp < NSPLIT; sp++) {
            for (int base = 0; base < cnts[sp]; base += 32) {
                int i = base + lane;
                bool valid = i < cnts[sp];
                unsigned long long c = valid ? cl[sp * SEGCAP + i] : 0ull;
                bool p = valid && (__int_as_float((int)(c >> 32)) <= thr);
                unsigned mask = __ballot_sync(0xffffffffu, p);
                if (p)
                    klist[wid][m + __popc(mask & ((1u << lane) - 1u))] = (int)(c & 0xffffffffu);
                m += __popc(mask);
            }
        }
        // pass 2: one chain round (m ~ 15 << 32)
        for (int i = lane; i < m; i += 32) {
            int k = klist[wid][i];
            float dv = exact_dist(n, k, emb);
            unsigned long long pk =
                ((unsigned long long)(unsigned)__float_as_int(dv) << 32) | (unsigned)k;
            if (pk < best) best = pk;
        }
    } else {
        for (int k = lane; k < KK; k += 32) {               // warp-parallel fallback
            float dv = exact_dist(n, k, emb);
            unsigned long long pk =
                ((unsigned long long)(unsigned)__float_as_int(dv) << 32) | (unsigned)k;
            if (pk < best) best = pk;
        }
    }
#pragma unroll
    for (int o = 16; o > 0; o >>= 1) {
        unsigned long long v = __shfl_xor_sync(0xffffffffu, best, o);
        if (v < best) best = v;
    }
    if (lane == 0) {
        int bk = (int)(best & 0xffffffffu);
        g_idx[n] = bk;
        out[ZQ_ELEMS + 1 + n] = (float)bk;
    }
}

// ---------------- gather + STE + loss ----------------
__global__ void vq_gather(const float* __restrict__ ze, const float* __restrict__ emb,
                          float* __restrict__ out) {
    __shared__ float sm[32 * 257];
    __shared__ double sred[256];
    int n0 = blockIdx.x * 32;
    int b = n0 >> 10, t0 = n0 & 1023;
    int tid = threadIdx.x;
    {
        int r = tid >> 3, c = tid & 7;
        int k = g_idx[n0 + r];
        const float4* er = (const float4*)(emb + (size_t)k * DD);
#pragma unroll
        for (int j = 0; j < 8; j++) {
            int ch = c + j * 8;
            float4 v = er[ch];
            sm[r * 257 + ch * 4 + 0] = v.x;
            sm[r * 257 + ch * 4 + 1] = v.y;
            sm[r * 257 + ch * 4 + 2] = v.z;
            sm[r * 257 + ch * 4 + 3] = v.w;
        }
    }
    __syncthreads();
    int w = tid >> 5, l = tid & 31;
    double lsum = 0.0;
#pragma unroll
    for (int j = 0; j < 32; j++) {
        int d = w * 32 + j;
        size_t off = ((size_t)b * DD + d) * TT + t0 + l;
        float e = sm[l * 257 + d];
        float v = ze[off];
        float diff = __fsub_rn(e, v);
        out[off] = __fadd_rn(v, diff);
        lsum += (double)__fmul_rn(diff, diff);
    }
    sred[tid] = lsum;
    __syncthreads();
    for (int s = 128; s > 0; s >>= 1) {
        if (tid < s) sred[tid] += sred[tid + s];
        __syncthreads();
    }
    if (tid == 0) atomicAdd(&g_loss, sred[0]);
}

__global__ void vq_finalize(float* __restrict__ out) {
    out[ZQ_ELEMS] = (float)(g_loss / (double)ZQ_ELEMS);
}

// ---------------- launch ----------------
extern "C" void kernel_launch(void* const* d_in, const int* in_sizes, int n_in,
                              void* d_out, int out_size) {
    (void)in_sizes; (void)n_in; (void)out_size;
    const float* ze = (const float*)d_in[0];
    const float* emb = (const float*)d_in[1];
    float* out = (float*)d_out;

    cudaFuncSetAttribute(vq_mma, cudaFuncAttributeMaxDynamicSharedMemorySize, DYN_BYTES);

    prep_eb<<<KK / 8, 256>>>(emb);                 // launch 1
    prep_x<<<NN / 32, 256>>>(ze);                  // launch 2
    zero_loss<<<1, 1>>>();                         // launch 3 (slot filler)
    vq_mma<<<256 * NSPLIT, 512, DYN_BYTES>>>();    // launch 4 <- profiler slot
    vq_refine<<<NN / 8, 256>>>(emb, out);          // launch 5
    vq_gather<<<NN / 32, 256>>>(ze, emb, out);     // launch 6
    vq_finalize<<<1, 1>>>(out);                    // launch 7
}